// round 15
// baseline (speedup 1.0000x reference)
#include <cuda_runtime.h>
#include <cstdint>

#define DINLINE __device__ __forceinline__

namespace {
constexpr int kTlen = 1024;
constexpr int kF = 64;
constexpr int kH = 256;
constexpr int kVRow = 324;   // padded vec row stride (floats)
constexpr int kVBuf = 16 * kVRow;  // one vec buffer (16 rows)
constexpr int kBT = 16;      // batch rows per CTA
constexpr int kNS = 16;      // k-slices; slice s = h[16s..16s+15] ++ x[4s..4s+3]
constexpr int kThreads = 256;
constexpr int kCtas = 128;   // 8 batch stripes x 16 hidden stripes
constexpr int kSmemBytes = 120 * 1024;  // force 1 CTA/SM
}

// h stored as per-producer PACKED tiles: g_h[buf][cta][b_local*16 + j_local]
__device__ float g_h[2][128 * 256];
__device__ unsigned g_flag[128 * 32];  // one monotonic flag per CTA, 128B apart

__global__ void init_barriers_kernel() {
  if (threadIdx.x < 128) g_flag[threadIdx.x * 32] = 0u;
}

DINLINE unsigned long long pack2(float lo, float hi) {
  unsigned long long r;
  asm("mov.b64 %0, {%1, %2};" : "=l"(r) : "f"(lo), "f"(hi));
  return r;
}
DINLINE void ffma2(unsigned long long& d, unsigned long long a, unsigned long long b) {
  asm("fma.rn.f32x2 %0, %1, %2, %0;" : "+l"(d) : "l"(a), "l"(b));
}
DINLINE float2 unpack2(unsigned long long v) {
  float lo, hi;
  asm("mov.b64 {%0, %1}, %2;" : "=f"(lo), "=f"(hi) : "l"(v));
  return make_float2(lo, hi);
}
DINLINE float tanh_fast(float x) {
  float y;
  asm("tanh.approx.f32 %0, %1;" : "=f"(y) : "f"(x));
  return y;
}
DINLINE float sigmoid_fast(float x) {
  return 0.5f * tanh_fast(0.5f * x) + 0.5f;
}

__global__ void __launch_bounds__(kThreads, 1)
lstm_seq2seq_kernel(const float* __restrict__ ts,
                    const float* __restrict__ Wih_e, const float* __restrict__ Whh_e,
                    const float* __restrict__ b_e,
                    const float* __restrict__ Wih_d, const float* __restrict__ Whh_d,
                    const float* __restrict__ b_d,
                    const float* __restrict__ Wout, const float* __restrict__ bout,
                    float* __restrict__ out) {
  extern __shared__ float smem[];
  float* vecs = smem;                          // [2][16][324] interleaved
  float* partial = smem + 2 * kVBuf;           // [16 slices][16 b][64] col=j*4+gate
  float* wout_s = partial + kNS * kBT * 64;    // [4][256]
  float* bout_s = wout_s + 4 * kH;             // [4]

  const int tid = threadIdx.x;
  const int warp = tid >> 5, lane = tid & 31;
  const int jstripe = blockIdx.x & 15;
  const int bstripe = blockIdx.x >> 4;

  const int slice = tid >> 4;   // 0..15 (GEMM k-slice; warp w owns slices 2w,2w+1)
  const int cg = tid & 15;      // 0..15 (local hidden col j)
  const int bl = tid >> 4;      // update: local batch row
  const int jj = tid & 15;      // update: local hidden col

  // x staging role: lane -> (row, slice)
  const int srow = lane >> 1;
  const int sslice = 2 * warp + (lane & 1);
  const unsigned* pflag = &g_flag[(bstripe * 16 + sslice) * 32];
  unsigned* myflag = &g_flag[blockIdx.x * 32];

  // prologue: publish h0 = 0 tile; stage W_out tile + b_out
  g_h[0][blockIdx.x * 256 + tid] = 0.0f;
  for (int idx = tid; idx < 4 * kH; idx += kThreads)
    wout_s[idx] = Wout[jstripe * 4 * kH + idx];
  if (tid < 4) bout_s[tid] = bout[jstripe * 4 + tid];
  __syncthreads();
  if (tid == 0)
    asm volatile("st.release.gpu.u32 [%0], %1;" :: "l"(myflag), "r"(1u) : "memory");

  unsigned long long w2[4][8];   // [gate][h k-pair], registers
  unsigned long long wx2[4][2];  // [gate][x k-pair]
  float bias[4];
  float cst = 0.0f;              // cell state, register-resident across all steps

  auto load_w = [&](const float* Wih, const float* Whh, const float* bv) {
#pragma unroll
    for (int cc = 0; cc < 4; ++cc) {
      const int row = cc * kH + jstripe * 16 + cg;
#pragma unroll
      for (int kp = 0; kp < 8; ++kp) {
        const int k = slice * 16 + 2 * kp;
        w2[cc][kp] = pack2(Whh[row * kH + k], Whh[row * kH + k + 1]);
      }
#pragma unroll
      for (int kp = 0; kp < 2; ++kp) {
        const int k = slice * 4 + 2 * kp;
        wx2[cc][kp] = pack2(Wih[row * kF + k], Wih[row * kF + k + 1]);
      }
    }
    const int jg = jstripe * 16 + jj;
#pragma unroll
    for (int g = 0; g < 4; ++g) bias[g] = bv[g * kH + jg];
  };

  // stage x(tnext) into vec[nbuf] x-slots + x-part of gate GEMM -> seeds partial
  auto xwork = [&](int tnext, int nbuf) {
    float* nvec = vecs + nbuf * kVBuf;
    {
      const float4 vx = *reinterpret_cast<const float4*>(
          ts + ((size_t)(bstripe * kBT + srow) * kTlen + tnext) * kF + sslice * 4);
      *reinterpret_cast<float4*>(nvec + srow * kVRow + sslice * 20 + 16) = vx;
    }
    __syncwarp();
    const float4* nvec4 = reinterpret_cast<const float4*>(nvec);
#pragma unroll
    for (int bg = 0; bg < 4; ++bg) {
      unsigned long long accA[4][4], accB[4][4];
#pragma unroll
      for (int bb = 0; bb < 4; ++bb)
#pragma unroll
        for (int cc = 0; cc < 4; ++cc) { accA[bb][cc] = 0ull; accB[bb][cc] = 0ull; }
#pragma unroll
      for (int bb = 0; bb < 4; ++bb) {
        const float4 vv = nvec4[(bg * 4 + bb) * (kVRow / 4) + slice * 5 + 4];
        const unsigned long long v0 = pack2(vv.x, vv.y);
        const unsigned long long v1 = pack2(vv.z, vv.w);
#pragma unroll
        for (int cc = 0; cc < 4; ++cc) ffma2(accA[bb][cc], v0, wx2[cc][0]);
#pragma unroll
        for (int cc = 0; cc < 4; ++cc) ffma2(accB[bb][cc], v1, wx2[cc][1]);
      }
#pragma unroll
      for (int bb = 0; bb < 4; ++bb) {
        float r[4];
#pragma unroll
        for (int cc = 0; cc < 4; ++cc) {
          const float2 fa = unpack2(accA[bb][cc]);
          const float2 fb = unpack2(accB[bb][cc]);
          r[cc] = (fa.x + fa.y) + (fb.x + fb.y);
        }
        *reinterpret_cast<float4*>(
            partial + (slice * kBT + bg * 4 + bb) * 64 + cg * 4) =
            make_float4(r[0], r[1], r[2], r[3]);
      }
    }
  };

  auto step = [&](unsigned gstep, int tt, bool dec, int tnext) {
    const int buf = (int)(gstep & 1u);
    float* vec = vecs + buf * kVBuf;
    const float4* vec4 = reinterpret_cast<const float4*>(vec);

    // per-warp wait: only this warp's two producers
    {
      const unsigned tgt = gstep + 1u;
      unsigned v; bool ok;
      do {
        asm volatile("ld.acquire.gpu.u32 %0, [%1];" : "=r"(v) : "l"(pflag));
        ok = (int)(v - tgt) >= 0;
      } while (!__all_sync(0xffffffffu, ok));
    }

    // stage this warp's two producer tiles (fully coalesced: 2KB contiguous)
    {
      const float4* t0 = reinterpret_cast<const float4*>(
          g_h[buf] + (bstripe * 16 + 2 * warp) * 256);
#pragma unroll
      for (int k = 0; k < 4; ++k) {
        const int flat = k * 32 + lane;        // 0..127 over 2 tiles
        const int s = 2 * warp + (flat >> 6);  // tile -> slice
        const int r = (flat >> 2) & 15;        // b row within tile
        const int c = flat & 3;                // float4 within row
        const float4 v = t0[flat];
        *reinterpret_cast<float4*>(vec + r * kVRow + s * 20 + c * 4) = v;
      }
    }
    __syncwarp();  // GEMM below reads only this warp's staged slices

    // h-GEMM (8 k-pairs), accumulating onto x-seeded partial (same-thread RMW)
#pragma unroll
    for (int bg = 0; bg < 4; ++bg) {
      unsigned long long accA[4][4], accB[4][4];
#pragma unroll
      for (int bb = 0; bb < 4; ++bb)
#pragma unroll
        for (int cc = 0; cc < 4; ++cc) { accA[bb][cc] = 0ull; accB[bb][cc] = 0ull; }
#pragma unroll
      for (int q = 0; q < 4; ++q) {   // 4 float4 = 16 h values per slice
#pragma unroll
        for (int bb = 0; bb < 4; ++bb) {
          const float4 vv = vec4[(bg * 4 + bb) * (kVRow / 4) + slice * 5 + q];
          const unsigned long long v0 = pack2(vv.x, vv.y);
          const unsigned long long v1 = pack2(vv.z, vv.w);
#pragma unroll
          for (int cc = 0; cc < 4; ++cc) ffma2(accA[bb][cc], v0, w2[cc][2 * q]);
#pragma unroll
          for (int cc = 0; cc < 4; ++cc) ffma2(accB[bb][cc], v1, w2[cc][2 * q + 1]);
        }
      }
#pragma unroll
      for (int bb = 0; bb < 4; ++bb) {
        float4* slot = reinterpret_cast<float4*>(
            partial + (slice * kBT + bg * 4 + bb) * 64 + cg * 4);
        const float4 xp = *slot;  // x contribution seeded post-publish last step
        float r[4];
#pragma unroll
        for (int cc = 0; cc < 4; ++cc) {
          const float2 fa = unpack2(accA[bb][cc]);
          const float2 fb = unpack2(accB[bb][cc]);
          r[cc] = (fa.x + fa.y) + (fb.x + fb.y);
        }
        *slot = make_float4(xp.x + r[0], xp.y + r[1], xp.z + r[2], xp.w + r[3]);
      }
    }
    __syncthreads();

    // reduce 16 slices (dual accumulator, one float4 per slice) + cell update
    {
      const float4* p4 = reinterpret_cast<const float4*>(partial);
      const int idx = bl * 16 + jj;
      float4 s0 = p4[idx];
      float4 s1 = p4[256 + idx];
#pragma unroll
      for (int sl = 2; sl < kNS; sl += 2) {
        const float4 a = p4[sl * 256 + idx];
        const float4 b = p4[(sl + 1) * 256 + idx];
        s0.x += a.x; s0.y += a.y; s0.z += a.z; s0.w += a.w;
        s1.x += b.x; s1.y += b.y; s1.z += b.z; s1.w += b.w;
      }
      const float ig = sigmoid_fast(s0.x + s1.x + bias[0]);
      const float fg = sigmoid_fast(s0.y + s1.y + bias[1]);
      const float gg = tanh_fast(s0.z + s1.z + bias[2]);
      const float og = sigmoid_fast(s0.w + s1.w + bias[3]);
      cst = fg * cst + ig * gg;
      const float hv = og * tanh_fast(cst);
      g_h[buf ^ 1][blockIdx.x * 256 + bl * 16 + jj] = hv;
    }
    __syncthreads();  // also orders reduce-reads of partial before xwork writes
    if (tid == 0) {
      const unsigned pub = gstep + 2u;
      asm volatile("st.release.gpu.u32 [%0], %1;" :: "l"(myflag), "r"(pub)
                   : "memory");
    }

    if (dec) {
      // out_t = h_pre @ Wout^T + bout — reads THIS step's vec buffer (off-path)
      const int o = tid >> 2, p = tid & 3;
      const int ob = o >> 2, ofi = o & 3;
      float s = 0.0f;
#pragma unroll
      for (int si = 0; si < 4; ++si) {
        const int sl = p * 4 + si;
        const float4* v4 =
            reinterpret_cast<const float4*>(vec + ob * kVRow + sl * 20);
        const float4* w4 =
            reinterpret_cast<const float4*>(wout_s + ofi * kH + sl * 16);
#pragma unroll
        for (int i = 0; i < 4; ++i) {
          const float4 a = v4[i], b = w4[i];
          s += a.x * b.x + a.y * b.y + a.z * b.z + a.w * b.w;
        }
      }
      s += __shfl_xor_sync(0xffffffffu, s, 1);
      s += __shfl_xor_sync(0xffffffffu, s, 2);
      if (p == 0)
        out[((bstripe * kBT + ob) * kTlen + tt) * kF + jstripe * 4 + ofi] =
            s + bout_s[ofi];
    }

    // post-publish idle window: stage x(tnext) + x-GEMM seeds next partial
    if (tnext >= 0) xwork(tnext, buf ^ 1);
  };

  // encoder: seed step 0, then iterate (step t seeds t+1; last step defers)
  load_w(Wih_e, Whh_e, b_e);
  xwork(0, 0);
  for (int t = 0; t < kTlen; ++t)
    step((unsigned)t, t, false, (t + 1 < kTlen) ? t + 1 : -1);

  // decoder: reload weights FIRST, then seed its step 0 with decoder x-weights
  load_w(Wih_d, Whh_d, b_d);
  xwork(kTlen - 1, 0);
  for (int i = 0; i < kTlen; ++i)
    step((unsigned)(kTlen + i), kTlen - 1 - i, true,
         (i + 1 < kTlen) ? kTlen - 2 - i : -1);
}

extern "C" void kernel_launch(void* const* d_in, const int* in_sizes, int n_in,
                              void* d_out, int out_size) {
  cudaFuncSetAttribute(lstm_seq2seq_kernel,
                       cudaFuncAttributeMaxDynamicSharedMemorySize, kSmemBytes);
  init_barriers_kernel<<<1, 128>>>();
  lstm_seq2seq_kernel<<<kCtas, kThreads, kSmemBytes>>>(
      (const float*)d_in[0], (const float*)d_in[1], (const float*)d_in[2],
      (const float*)d_in[3], (const float*)d_in[4], (const float*)d_in[5],
      (const float*)d_in[6], (const float*)d_in[7], (const float*)d_in[8],
      (float*)d_out);
}

// round 16
// speedup vs baseline: 1.1164x; 1.1164x over previous
#include <cuda_runtime.h>
#include <cstdint>

#define DINLINE __device__ __forceinline__

namespace {
constexpr int kTlen = 1024;
constexpr int kF = 64;
constexpr int kH = 256;
constexpr int kVRow = 324;   // 8 slices x 40 (32h+8x) = 320, +4 pad
constexpr int kVBuf = 8 * kVRow;   // one vec buffer (8 rows)
constexpr int kBT = 8;       // batch rows per CTA
constexpr int kNS = 8;       // k-slices == producers per group
constexpr int kThreads = 256;
constexpr int kCtas = 128;   // 16 batch stripes x 8 hidden stripes
constexpr int kSmemBytes = 120 * 1024;  // force 1 CTA/SM
}

// h stored as per-producer PACKED tiles: g_h[buf][cta][b_local*32 + j_local]
__device__ float g_h[2][128 * 256];
__device__ unsigned g_flag[128 * 32];  // one monotonic flag per CTA, 128B apart

__global__ void init_barriers_kernel() {
  if (threadIdx.x < 128) g_flag[threadIdx.x * 32] = 0u;
}

DINLINE unsigned long long pack2(float lo, float hi) {
  unsigned long long r;
  asm("mov.b64 %0, {%1, %2};" : "=l"(r) : "f"(lo), "f"(hi));
  return r;
}
DINLINE void ffma2(unsigned long long& d, unsigned long long a, unsigned long long b) {
  asm("fma.rn.f32x2 %0, %1, %2, %0;" : "+l"(d) : "l"(a), "l"(b));
}
DINLINE float2 unpack2(unsigned long long v) {
  float lo, hi;
  asm("mov.b64 {%0, %1}, %2;" : "=f"(lo), "=f"(hi) : "l"(v));
  return make_float2(lo, hi);
}
DINLINE float tanh_fast(float x) {
  float y;
  asm("tanh.approx.f32 %0, %1;" : "=f"(y) : "f"(x));
  return y;
}
DINLINE float sigmoid_fast(float x) {
  return 0.5f * tanh_fast(0.5f * x) + 0.5f;
}

__global__ void __launch_bounds__(kThreads, 1)
lstm_seq2seq_kernel(const float* __restrict__ ts,
                    const float* __restrict__ Wih_e, const float* __restrict__ Whh_e,
                    const float* __restrict__ b_e,
                    const float* __restrict__ Wih_d, const float* __restrict__ Whh_d,
                    const float* __restrict__ b_d,
                    const float* __restrict__ Wout, const float* __restrict__ bout,
                    float* __restrict__ out) {
  extern __shared__ float smem[];
  float* vecs = smem;                          // [2][8][324] interleaved
  float* partial = smem + 2 * kVBuf;           // [8 slices][8 b][128] col=j*4+gate
  float* wout_s = partial + kNS * kBT * 128;   // [8][256]
  float* bout_s = wout_s + 8 * kH;             // [8]

  const int tid = threadIdx.x;
  const int warp = tid >> 5, lane = tid & 31;
  const int jstripe = blockIdx.x & 7;          // 0..7  hidden stripe (32 j each)
  const int bstripe = blockIdx.x >> 3;         // 0..15 batch stripe (8 rows each)

  const int slice = warp;       // warp w owns slice w == producer w
  const int cg = lane;          // 0..31 local hidden col j
  const int bl = tid >> 5;      // update: local batch row (0..7)
  const int jj = tid & 31;      // update: local hidden col (0..31)

  const unsigned* pflag = &g_flag[(bstripe * 8 + warp) * 32];
  unsigned* myflag = &g_flag[blockIdx.x * 32];

  // prologue: publish h0 = 0 tile; stage W_out rows + b_out
  g_h[0][blockIdx.x * 256 + tid] = 0.0f;
  for (int idx = tid; idx < 8 * kH; idx += kThreads)
    wout_s[idx] = Wout[jstripe * 8 * kH + idx];
  if (tid < 8) bout_s[tid] = bout[jstripe * 8 + tid];
  __syncthreads();
  if (tid == 0)
    asm volatile("st.release.gpu.u32 [%0], %1;" :: "l"(myflag), "r"(1u) : "memory");

  unsigned long long w2[4][20];  // [gate][k-pair]: 16 h pairs + 4 x pairs
  float bias[4];
  float cst = 0.0f;              // cell state, register-resident across all steps

  auto load_w = [&](const float* Wih, const float* Whh, const float* bv) {
#pragma unroll
    for (int cc = 0; cc < 4; ++cc) {
      const int row = cc * kH + jstripe * 32 + cg;
#pragma unroll
      for (int kp = 0; kp < 16; ++kp) {
        const int k = slice * 32 + 2 * kp;
        w2[cc][kp] = pack2(Whh[row * kH + k], Whh[row * kH + k + 1]);
      }
#pragma unroll
      for (int kp = 0; kp < 4; ++kp) {
        const int k = slice * 8 + 2 * kp;
        w2[cc][16 + kp] = pack2(Wih[row * kF + k], Wih[row * kF + k + 1]);
      }
    }
    const int jg = jstripe * 32 + jj;
#pragma unroll
    for (int g = 0; g < 4; ++g) bias[g] = bv[g * kH + jg];
  };

  auto step = [&](unsigned gstep, int tt, bool dec) {
    const int buf = (int)(gstep & 1u);
    float* vec = vecs + buf * kVBuf;
    const float4* vec4 = reinterpret_cast<const float4*>(vec);

    // pre-stage x(tt) into own slice's x-slots (flag-independent)
    if (lane < 16) {
      const int r = lane >> 1, c = lane & 1;
      const float4 vx = *reinterpret_cast<const float4*>(
          ts + ((size_t)(bstripe * kBT + r) * kTlen + tt) * kF + slice * 8 + c * 4);
      *reinterpret_cast<float4*>(vec + r * kVRow + slice * 40 + 32 + c * 4) = vx;
    }

    // per-warp wait: exactly ONE producer; all lanes poll same flag (broadcast)
    {
      const unsigned tgt = gstep + 1u;
      unsigned v;
      do {
        asm volatile("ld.acquire.gpu.u32 %0, [%1];" : "=r"(v) : "l"(pflag));
      } while ((int)(v - tgt) < 0);
    }

    // stage producer w's packed tile (8b x 32j = 64 float4, fully coalesced)
    {
      const float4* t0 = reinterpret_cast<const float4*>(
          g_h[buf] + (bstripe * 8 + slice) * 256);
#pragma unroll
      for (int it = 0; it < 2; ++it) {
        const int flat = it * 32 + lane;       // 0..63
        const int r = flat >> 3, c = flat & 7; // row, float4 col
        const float4 v = t0[flat];
        *reinterpret_cast<float4*>(vec + r * kVRow + slice * 40 + c * 4) = v;
      }
    }
    __syncwarp();  // GEMM below reads only this warp's staged slice

    // gate GEMM (own slice, 40 k): single acc (16 indep chains), weights in regs
#pragma unroll
    for (int bg = 0; bg < 2; ++bg) {
      unsigned long long acc[4][4];
#pragma unroll
      for (int bb = 0; bb < 4; ++bb)
#pragma unroll
        for (int cc = 0; cc < 4; ++cc) acc[bb][cc] = 0ull;
#pragma unroll
      for (int q = 0; q < 10; ++q) {   // 10 float4 = 40 k values (32h + 8x)
#pragma unroll
        for (int bb = 0; bb < 4; ++bb) {
          const float4 vv = vec4[(bg * 4 + bb) * (kVRow / 4) + slice * 10 + q];
          const unsigned long long v0 = pack2(vv.x, vv.y);
          const unsigned long long v1 = pack2(vv.z, vv.w);
#pragma unroll
          for (int cc = 0; cc < 4; ++cc) ffma2(acc[bb][cc], v0, w2[cc][2 * q]);
#pragma unroll
          for (int cc = 0; cc < 4; ++cc) ffma2(acc[bb][cc], v1, w2[cc][2 * q + 1]);
        }
      }
#pragma unroll
      for (int bb = 0; bb < 4; ++bb) {
        float r[4];
#pragma unroll
        for (int cc = 0; cc < 4; ++cc) {
          const float2 f = unpack2(acc[bb][cc]);
          r[cc] = f.x + f.y;
        }
        *reinterpret_cast<float4*>(
            partial + (slice * kBT + bg * 4 + bb) * 128 + cg * 4) =
            make_float4(r[0], r[1], r[2], r[3]);
      }
    }
    __syncthreads();

    // reduce 8 slices (dual accumulator, one float4 per slice) + cell update
    {
      const float4* p4 = reinterpret_cast<const float4*>(partial);
      const int idx = bl * 32 + jj;            // float4 index within slice plane
      float4 s0 = p4[idx];
      float4 s1 = p4[256 + idx];               // slice plane = 8*128/4 = 256
#pragma unroll
      for (int sl = 2; sl < kNS; sl += 2) {
        const float4 a = p4[sl * 256 + idx];
        const float4 b = p4[(sl + 1) * 256 + idx];
        s0.x += a.x; s0.y += a.y; s0.z += a.z; s0.w += a.w;
        s1.x += b.x; s1.y += b.y; s1.z += b.z; s1.w += b.w;
      }
      const float ig = sigmoid_fast(s0.x + s1.x + bias[0]);
      const float fg = sigmoid_fast(s0.y + s1.y + bias[1]);
      const float gg = tanh_fast(s0.z + s1.z + bias[2]);
      const float og = sigmoid_fast(s0.w + s1.w + bias[3]);
      cst = fg * cst + ig * gg;
      const float hv = og * tanh_fast(cst);
      // publish packed tile: g_h[buf^1][cta][bl*32 + jj] (coalesced)
      g_h[buf ^ 1][blockIdx.x * 256 + bl * 32 + jj] = hv;
    }
    __syncthreads();
    if (tid == 0) {
      const unsigned pub = gstep + 2u;
      asm volatile("st.release.gpu.u32 [%0], %1;" :: "l"(myflag), "r"(pub)
                   : "memory");
    }

    if (dec) {
      // out_t = h_pre @ Wout^T + bout — off the serial path, reads this buf
      const int o = tid >> 2, p = tid & 3;     // 64 outputs x 4-way split-K
      const int ob = o >> 3, ofi = o & 7;      // b row 0..7, f 0..7
      float s = 0.0f;
#pragma unroll
      for (int si = 0; si < 2; ++si) {
        const int sl = p * 2 + si;
        const float4* v4 =
            reinterpret_cast<const float4*>(vec + ob * kVRow + sl * 40);
        const float4* w4 =
            reinterpret_cast<const float4*>(wout_s + ofi * kH + sl * 32);
#pragma unroll
        for (int i = 0; i < 8; ++i) {
          const float4 a = v4[i], b = w4[i];
          s += a.x * b.x + a.y * b.y + a.z * b.z + a.w * b.w;
        }
      }
      s += __shfl_xor_sync(0xffffffffu, s, 1);
      s += __shfl_xor_sync(0xffffffffu, s, 2);
      if (p == 0)
        out[((bstripe * kBT + ob) * kTlen + tt) * kF + jstripe * 8 + ofi] =
            s + bout_s[ofi];
    }
  };

  load_w(Wih_e, Whh_e, b_e);
  for (int t = 0; t < kTlen; ++t) step((unsigned)t, t, false);

  load_w(Wih_d, Whh_d, b_d);
  for (int i = 0; i < kTlen; ++i)
    step((unsigned)(kTlen + i), kTlen - 1 - i, true);
}

extern "C" void kernel_launch(void* const* d_in, const int* in_sizes, int n_in,
                              void* d_out, int out_size) {
  cudaFuncSetAttribute(lstm_seq2seq_kernel,
                       cudaFuncAttributeMaxDynamicSharedMemorySize, kSmemBytes);
  init_barriers_kernel<<<1, 128>>>();
  lstm_seq2seq_kernel<<<kCtas, kThreads, kSmemBytes>>>(
      (const float*)d_in[0], (const float*)d_in[1], (const float*)d_in[2],
      (const float*)d_in[3], (const float*)d_in[4], (const float*)d_in[5],
      (const float*)d_in[6], (const float*)d_in[7], (const float*)d_in[8],
      (float*)d_out);
}